// round 16
// baseline (speedup 1.0000x reference)
#include <cuda_runtime.h>
#include <cuda_fp16.h>
#include <math.h>
#include <stdint.h>

#define NH   16
#define HD   64
#define KW   13
#define CDIM 1024
#define BB   4
#define LL   4096
#define MM   (BB*LL)        // 16384
#define NQKV (3*CDIM)       // 3072
#define QK_SCALE 0.125f
#define RPB_W (2*KW-1)      // 25

// ---------------- device-global scratch (no allocation allowed) --------------
__device__ __half g_q[(size_t)BB*NH*LL*HD];
__device__ __half g_k[(size_t)BB*NH*LL*HD];
__device__ __half g_v[(size_t)BB*NH*LL*HD];

// activations as fp16 (single term)
__device__ __half g_xhi[(size_t)MM*CDIM];
__device__ __half g_ahi[(size_t)MM*CDIM];

// weights: transposed [N,K], single fp16 (rounded)
__device__ __half g_wqkvT[(size_t)NQKV*CDIM];
__device__ __half g_wprojT[(size_t)CDIM*CDIM];

// ---------------- helpers (sm_80+ ISA, valid on sm_103 target) ---------------
__device__ __forceinline__ uint32_t smem_u32(const void* p) {
    uint32_t a;
    asm("{ .reg .u64 t; cvta.to.shared.u64 t, %1; cvt.u32.u64 %0, t; }"
        : "=r"(a) : "l"(p));
    return a;
}
__device__ __forceinline__ void ldsm4(uint32_t* r, uint32_t addr) {
    asm volatile("ldmatrix.sync.aligned.m8n8.x4.shared.b16 {%0,%1,%2,%3}, [%4];"
        : "=r"(r[0]), "=r"(r[1]), "=r"(r[2]), "=r"(r[3]) : "r"(addr));
}
__device__ __forceinline__ void mma16816(float* c, const uint32_t* a, const uint32_t* b) {
    asm volatile("mma.sync.aligned.m16n8k16.row.col.f32.f16.f16.f32 "
        "{%0,%1,%2,%3}, {%4,%5,%6,%7}, {%8,%9}, {%0,%1,%2,%3};"
        : "+f"(c[0]), "+f"(c[1]), "+f"(c[2]), "+f"(c[3])
        : "r"(a[0]), "r"(a[1]), "r"(a[2]), "r"(a[3]), "r"(b[0]), "r"(b[1]));
}
__device__ __forceinline__ void cp16(uint32_t smem, const void* gmem) {
    asm volatile("cp.async.cg.shared.global [%0], [%1], 16;" :: "r"(smem), "l"(gmem));
}

// ---------------- pre-pass: convert fp32 x -> fp16 ---------------------------
__global__ __launch_bounds__(256, 4)
void split_kernel(const float* __restrict__ src, int n4)
{
    const int i = blockIdx.x * 256 + threadIdx.x;
    if (i >= n4) return;
    float4 v = ((const float4*)src)[i];
    __half2* hip = (__half2*)(g_xhi + (size_t)i * 4);
    hip[0] = __halves2half2(__float2half(v.x), __float2half(v.y));
    hip[1] = __halves2half2(__float2half(v.z), __float2half(v.w));
}

// ---------------- pre-pass: transpose BOTH weights [K,N] -> [N,K] fp16 -------
// blockIdx.x in [0,96): w_qkv (N=3072); [96,128): w_proj (N=1024). K=1024 both.
__global__ __launch_bounds__(256, 4)
void transpose_both_kernel(const float* __restrict__ wqkv, const float* __restrict__ wproj)
{
    __shared__ float t[32][33];
    const int bx = blockIdx.x;
    const bool is_proj = (bx >= NQKV / 32);
    const float* w = is_proj ? wproj : wqkv;
    __half* wT     = is_proj ? g_wprojT : g_wqkvT;
    const int N    = is_proj ? CDIM : NQKV;
    const int n0   = (is_proj ? (bx - NQKV / 32) : bx) * 32;
    const int k0   = blockIdx.y * 32;
    const int tx = threadIdx.x;           // 0..31
    const int ty = threadIdx.y;           // 0..7
    #pragma unroll
    for (int i = 0; i < 4; i++) {
        const int k = k0 + ty + i * 8;
        t[ty + i*8][tx] = w[(size_t)k * N + n0 + tx];
    }
    __syncthreads();
    #pragma unroll
    for (int i = 0; i < 4; i++) {
        const int n = n0 + ty + i * 8;
        wT[(size_t)n * CDIM + k0 + tx] = __float2half(t[tx][ty + i*8]);
    }
}

// ---------------- fp16 1-term tensor-core GEMM, 4-stage cp.async -------------
// MODE 0 (QKV): scatter epilogue (+bias, q scale) -> fp16 q/k/v.
// MODE 1 (proj): plain +bias fp32 -> d_out.
#define BK  32
#define LDA 40                       // padded smem stride (fp16 elems)
#define TILE_B (128*LDA*2)           // 10240 bytes per tile
#define STAGE_B (2*TILE_B)           // A, B
#define NSTAGE 4
#define GEMM_SMEM (NSTAGE*STAGE_B)   // 81920 B

template<int MODE>
__global__ __launch_bounds__(256, 2)
void gemm_mma_kernel(const float* __restrict__ bias, float* __restrict__ C)
{
    extern __shared__ __align__(16) char dsm[];
    const uint32_t u0 = smem_u32(dsm);

    const __half* __restrict__ Ahi = MODE ? g_ahi : g_xhi;
    const __half* __restrict__ Bw  = MODE ? g_wprojT : g_wqkvT;

    const int tid = threadIdx.x;
    const int wid = tid >> 5;
    const int lid = tid & 31;
    const int wm  = wid & 1;         // 0..1  (M)
    const int wn  = wid >> 1;        // 0..3  (N)
    const int m0  = blockIdx.y * 128;
    const int n0  = blockIdx.x * 128;

    // gmem load mapping: 64 rows/pass, 8 fp16 (16B) per thread, 2 passes
    const int lrow = tid >> 2;            // 0..63
    const int lcol = (tid & 3) * 8;       // 0,8,16,24

    const size_t gA0 = (size_t)(m0 + lrow)      * CDIM + lcol;
    const size_t gA1 = (size_t)(m0 + lrow + 64) * CDIM + lcol;
    const size_t gB0 = (size_t)(n0 + lrow)      * CDIM + lcol;
    const size_t gB1 = (size_t)(n0 + lrow + 64) * CDIM + lcol;
    const uint32_t so0 = (uint32_t)((lrow        * LDA + lcol) * 2);
    const uint32_t so1 = (uint32_t)(((lrow + 64) * LDA + lcol) * 2);

    // ldmatrix lane addressing (R11 scheme)
    const int aRow  = wm * 64 + (lid & 15);
    const int aKoff = (lid >> 4) * 8;
    const int bRowX = wn * 32 + (lid & 7) + ((lid >> 4) * 8);
    const int bKoff = ((lid >> 3) & 1) * 8;

    float acc[4][4][4];
    #pragma unroll
    for (int t = 0; t < 4; t++)
        #pragma unroll
        for (int u = 0; u < 4; u++)
            #pragma unroll
            for (int e = 0; e < 4; e++) acc[t][u][e] = 0.f;

#define ISSUE(chunk, stage) do {                                          \
        const int _k0 = (chunk) * BK;                                     \
        const uint32_t _sb = u0 + (stage) * STAGE_B;                      \
        cp16(_sb + 0*TILE_B + so0, Ahi + gA0 + _k0);                      \
        cp16(_sb + 0*TILE_B + so1, Ahi + gA1 + _k0);                      \
        cp16(_sb + 1*TILE_B + so0, Bw  + gB0 + _k0);                      \
        cp16(_sb + 1*TILE_B + so1, Bw  + gB1 + _k0);                      \
        asm volatile("cp.async.commit_group;" ::: "memory");              \
    } while (0)

    const int steps = CDIM / BK;     // 32
    ISSUE(0, 0);
    ISSUE(1, 1);
    ISSUE(2, 2);

    for (int c = 0; c < steps; c++) {
        if (c + 2 < steps)
            asm volatile("cp.async.wait_group 2;" ::: "memory");
        else if (c + 1 < steps)
            asm volatile("cp.async.wait_group 1;" ::: "memory");
        else
            asm volatile("cp.async.wait_group 0;" ::: "memory");
        __syncthreads();

        if (c + 3 < steps) ISSUE(c + 3, (c + 3) & 3);

        const uint32_t sb  = u0 + (c & 3) * STAGE_B;
        const uint32_t uAh = sb;
        const uint32_t uB  = sb + 1 * TILE_B;

        #pragma unroll
        for (int s = 0; s < 2; s++) {
            const int ak = aKoff + s * 16;
            const int bk = bKoff + s * 16;
            uint32_t ah[4][4], bw[2][4];   // bw[p] covers u=2p,2p+1

            #pragma unroll
            for (int t = 0; t < 4; t++)
                ldsm4(ah[t], uAh + (uint32_t)(((aRow + t*16) * LDA + ak) * 2));
            #pragma unroll
            for (int p = 0; p < 2; p++)
                ldsm4(bw[p], uB + (uint32_t)(((bRowX + p*16) * LDA + bk) * 2));

            #pragma unroll
            for (int t = 0; t < 4; t++)
                #pragma unroll
                for (int u = 0; u < 4; u++)
                    mma16816(acc[t][u], ah[t], &bw[u >> 1][(u & 1) * 2]);
        }
    }
#undef ISSUE

    // ---- epilogue (pairs share m, consecutive n) ----
    const int g   = lid >> 2;      // 0..7
    const int tig = lid & 3;       // 0..3
    #pragma unroll
    for (int t = 0; t < 4; t++) {
        #pragma unroll
        for (int u = 0; u < 4; u++) {
            #pragma unroll
            for (int ep = 0; ep < 2; ep++) {
                const int m = m0 + wm*64 + t*16 + g + (ep ? 8 : 0);
                const int n = n0 + wn*32 + u*8 + tig*2;
                float2 v2;
                v2.x = acc[t][u][ep*2 + 0] + bias[n];
                v2.y = acc[t][u][ep*2 + 1] + bias[n + 1];
                if (MODE == 0) {
                    const int b_  = m >> 12;
                    const int l   = m & (LL - 1);
                    const int wch = n >> 10;
                    const int rem = n & 1023;
                    const int h   = rem >> 6;
                    const int dd  = rem & 63;
                    const size_t idx = (((size_t)(b_ * NH + h)) * LL + l) * HD + dd;
                    if (wch == 0) {
                        __half2 hv = __halves2half2(__float2half(v2.x * QK_SCALE),
                                                    __float2half(v2.y * QK_SCALE));
                        *(__half2*)&g_q[idx] = hv;
                    } else if (wch == 1) {
                        *(__half2*)&g_k[idx] = __halves2half2(__float2half(v2.x),
                                                              __float2half(v2.y));
                    } else {
                        *(__half2*)&g_v[idx] = __halves2half2(__float2half(v2.x),
                                                              __float2half(v2.y));
                    }
                } else {
                    *(float2*)&C[(size_t)m * CDIM + n] = v2;
                }
            }
        }
    }
}

// ---------------- NA1D attention: single-phase, K+V tiles resident ----------
#define TROWS 140
#define ROWP  68   // 17 float4s per row: 16B-aligned, conflict-free LDS.128
#define NA1D_SMEM ((2*TROWS*ROWP + RPB_W + 3) * (int)sizeof(float))

__global__ __launch_bounds__(128, 1)
void na1d_kernel(const float* __restrict__ rpb)
{
    extern __shared__ __align__(16) float sh[];
    float* ksh = sh;                       // [TROWS][ROWP]
    float* vsh = sh + TROWS * ROWP;        // [TROWS][ROWP]
    float* rsh = vsh + TROWS * ROWP;       // [RPB_W]

    const int tid = threadIdx.x;
    const int l0  = blockIdx.x * 128;
    const int h   = blockIdx.y;
    const int b   = blockIdx.z;

    const size_t head_base = ((size_t)(b * NH + h)) * LL * HD;
    const int kbase = min(max(l0 - (KW / 2), 0), LL - KW);
    const int krows = min(TROWS, LL - kbase);

    // ---- load K and V tiles together (uint4 = 8 halves/load, fp32 smem) ----
    const __half* kp = g_k + head_base + (size_t)kbase * HD;
    const __half* vp = g_v + head_base + (size_t)kbase * HD;
    for (int idx = tid; idx < krows * 8; idx += 128) {
        const int rr = idx >> 3;
        const int c8 = (idx & 7);
        uint4 kraw = *(const uint4*)(kp + (size_t)rr * HD + c8 * 8);
        uint4 vraw = *(const uint4*)(vp + (size_t)rr * HD + c8 * 8);
        const __half2* kh = (const __half2*)&kraw;
        const __half2* vh = (const __half2*)&vraw;
        float* kd = &ksh[rr * ROWP + c8 * 8];
        float* vd = &vsh[rr * ROWP + c8 * 8];
        #pragma unroll
        for (int j = 0; j < 4; j++) {
            float2 kf = __half22float2(kh[j]);
            float2 vf = __half22float2(vh[j]);
            kd[j*2+0] = kf.x; kd[j*2+1] = kf.y;
            vd[j*2+0] = vf.x; vd[j*2+1] = vf.y;
        }
    }
    if (tid < RPB_W) rsh[tid] = rpb[h * RPB_W + tid];

    const int l = l0 + tid;
    // q in registers (fp16 gmem loads -> fp32); overlaps with smem fill
    float q[HD];
    {
        const __half* qp = g_q + head_base + (size_t)l * HD;
        #pragma unroll
        for (int c8 = 0; c8 < 8; c8++) {
            uint4 raw = *(const uint4*)(qp + c8 * 8);
            const __half2* h2 = (const __half2*)&raw;
            #pragma unroll
            for (int j = 0; j < 4; j++) {
                float2 f = __half22float2(h2[j]);
                q[c8*8 + j*2 + 0] = f.x;
                q[c8*8 + j*2 + 1] = f.y;
            }
        }
    }
    __syncthreads();

    const int ni = min(max(l - (KW / 2), 0), LL - KW);
    const int r0 = ni - kbase;
    const int bias0 = ni - l + (KW - 1);

    float logits[KW];
    #pragma unroll
    for (int kk = 0; kk < KW; kk++) {
        const float* kr = &ksh[(r0 + kk) * ROWP];
        float s = 0.f;
        #pragma unroll
        for (int d = 0; d < HD; d++) s = fmaf(q[d], kr[d], s);
        logits[kk] = s + rsh[bias0 + kk];
    }

    float mx = logits[0];
    #pragma unroll
    for (int kk = 1; kk < KW; kk++) mx = fmaxf(mx, logits[kk]);
    float ssum = 0.f;
    #pragma unroll
    for (int kk = 0; kk < KW; kk++) { logits[kk] = expf(logits[kk] - mx); ssum += logits[kk]; }
    const float inv = 1.f / ssum;

    float4 acc4[16];
    #pragma unroll
    for (int d4 = 0; d4 < 16; d4++) acc4[d4] = make_float4(0.f, 0.f, 0.f, 0.f);
    #pragma unroll
    for (int kk = 0; kk < KW; kk++) {
        const float w = logits[kk] * inv;
        const float4* vr = (const float4*)&vsh[(r0 + kk) * ROWP];
        #pragma unroll
        for (int d4 = 0; d4 < 16; d4++) {
            float4 vv = vr[d4];
            acc4[d4].x = fmaf(w, vv.x, acc4[d4].x);
            acc4[d4].y = fmaf(w, vv.y, acc4[d4].y);
            acc4[d4].z = fmaf(w, vv.z, acc4[d4].z);
            acc4[d4].w = fmaf(w, vv.w, acc4[d4].w);
        }
    }

    // ---- fp16 output: 8x 16B stores ----
    const size_t obase = ((size_t)b * LL + l) * CDIM + h * HD;
    uint4* oh4 = (uint4*)(g_ahi + obase);
    #pragma unroll
    for (int v8 = 0; v8 < 8; v8++) {        // 8 halves (16B) per iteration
        __half2 hh[4];
        #pragma unroll
        for (int p = 0; p < 4; p++) {       // 2 floats per pair
            const int d4 = v8 * 2 + (p >> 1);
            const float f0 = (p & 1) ? ((const float*)&acc4[d4])[2]
                                     : ((const float*)&acc4[d4])[0];
            const float f1 = (p & 1) ? ((const float*)&acc4[d4])[3]
                                     : ((const float*)&acc4[d4])[1];
            hh[p] = __halves2half2(__float2half(f0), __float2half(f1));
        }
        uint4 hv;
        hv.x = *(uint32_t*)&hh[0]; hv.y = *(uint32_t*)&hh[1];
        hv.z = *(uint32_t*)&hh[2]; hv.w = *(uint32_t*)&hh[3];
        oh4[v8] = hv;
    }
}

// ---------------- launch ------------------------------------------------------
extern "C" void kernel_launch(void* const* d_in, const int* in_sizes, int n_in,
                              void* d_out, int out_size)
{
    const float* x      = (const float*)d_in[0];
    const float* w_qkv  = (const float*)d_in[1];
    const float* b_qkv  = (const float*)d_in[2];
    const float* rpb    = (const float*)d_in[3];
    const float* w_proj = (const float*)d_in[4];
    const float* b_proj = (const float*)d_in[5];
    float* out = (float*)d_out;

    cudaFuncSetAttribute(gemm_mma_kernel<0>, cudaFuncAttributeMaxDynamicSharedMemorySize, GEMM_SMEM);
    cudaFuncSetAttribute(gemm_mma_kernel<1>, cudaFuncAttributeMaxDynamicSharedMemorySize, GEMM_SMEM);
    cudaFuncSetAttribute(na1d_kernel, cudaFuncAttributeMaxDynamicSharedMemorySize, NA1D_SMEM);

    // 0) convert x to fp16
    {
        const int n4 = MM * CDIM / 4;
        split_kernel<<<(n4 + 255) / 256, 256>>>(x, n4);
    }
    // 0b) transpose both weights -> fp16 [N,K] (single launch)
    {
        dim3 grid((NQKV + CDIM) / 32, CDIM / 32);
        transpose_both_kernel<<<grid, dim3(32, 8)>>>(w_qkv, w_proj);
    }

    // 1) QKV GEMM (tensor cores, 1-term) -> scatter fp16 q/k/v
    {
        dim3 grid(NQKV / 128, MM / 128);
        gemm_mma_kernel<0><<<grid, 256, GEMM_SMEM>>>(b_qkv, nullptr);
    }

    // 2) NA1D attention -> fp16 attn output
    {
        dim3 grid(LL / 128, NH, BB);
        na1d_kernel<<<grid, 128, NA1D_SMEM>>>(rpb);
    }

    // 3) proj GEMM (tensor cores, 1-term) -> d_out
    {
        dim3 grid(CDIM / 128, MM / 128);
        gemm_mma_kernel<1><<<grid, 256, GEMM_SMEM>>>(b_proj, out);
    }
}

// round 17
// speedup vs baseline: 1.0247x; 1.0247x over previous
#include <cuda_runtime.h>
#include <cuda_fp16.h>
#include <math.h>
#include <stdint.h>

#define NH   16
#define HD   64
#define KW   13
#define CDIM 1024
#define BB   4
#define LL   4096
#define MM   (BB*LL)        // 16384
#define NQKV (3*CDIM)       // 3072
#define QK_SCALE 0.125f
#define RPB_W (2*KW-1)      // 25

// ---------------- device-global scratch (no allocation allowed) --------------
__device__ __half g_q[(size_t)BB*NH*LL*HD];
__device__ __half g_k[(size_t)BB*NH*LL*HD];
__device__ __half g_v[(size_t)BB*NH*LL*HD];

// activations as fp16 (single term)
__device__ __half g_xhi[(size_t)MM*CDIM];
__device__ __half g_ahi[(size_t)MM*CDIM];

// weights: transposed [N,K], single fp16 (rounded)
__device__ __half g_wqkvT[(size_t)NQKV*CDIM];
__device__ __half g_wprojT[(size_t)CDIM*CDIM];

// ---------------- helpers (sm_80+ ISA, valid on sm_103 target) ---------------
__device__ __forceinline__ uint32_t smem_u32(const void* p) {
    uint32_t a;
    asm("{ .reg .u64 t; cvta.to.shared.u64 t, %1; cvt.u32.u64 %0, t; }"
        : "=r"(a) : "l"(p));
    return a;
}
__device__ __forceinline__ void ldsm4(uint32_t* r, uint32_t addr) {
    asm volatile("ldmatrix.sync.aligned.m8n8.x4.shared.b16 {%0,%1,%2,%3}, [%4];"
        : "=r"(r[0]), "=r"(r[1]), "=r"(r[2]), "=r"(r[3]) : "r"(addr));
}
__device__ __forceinline__ void mma16816(float* c, const uint32_t* a, const uint32_t* b) {
    asm volatile("mma.sync.aligned.m16n8k16.row.col.f32.f16.f16.f32 "
        "{%0,%1,%2,%3}, {%4,%5,%6,%7}, {%8,%9}, {%0,%1,%2,%3};"
        : "+f"(c[0]), "+f"(c[1]), "+f"(c[2]), "+f"(c[3])
        : "r"(a[0]), "r"(a[1]), "r"(a[2]), "r"(a[3]), "r"(b[0]), "r"(b[1]));
}
__device__ __forceinline__ void cp16(uint32_t smem, const void* gmem) {
    asm volatile("cp.async.cg.shared.global [%0], [%1], 16;" :: "r"(smem), "l"(gmem));
}

// ---------------- pre-pass: convert fp32 x -> fp16 ---------------------------
__global__ __launch_bounds__(256, 4)
void split_kernel(const float* __restrict__ src, int n4)
{
    const int i = blockIdx.x * 256 + threadIdx.x;
    if (i >= n4) return;
    float4 v = ((const float4*)src)[i];
    __half2* hip = (__half2*)(g_xhi + (size_t)i * 4);
    hip[0] = __halves2half2(__float2half(v.x), __float2half(v.y));
    hip[1] = __halves2half2(__float2half(v.z), __float2half(v.w));
}

// ---------------- pre-pass: transpose BOTH weights [K,N] -> [N,K] fp16 -------
__global__ __launch_bounds__(256, 4)
void transpose_both_kernel(const float* __restrict__ wqkv, const float* __restrict__ wproj)
{
    __shared__ float t[32][33];
    const int bx = blockIdx.x;
    const bool is_proj = (bx >= NQKV / 32);
    const float* w = is_proj ? wproj : wqkv;
    __half* wT     = is_proj ? g_wprojT : g_wqkvT;
    const int N    = is_proj ? CDIM : NQKV;
    const int n0   = (is_proj ? (bx - NQKV / 32) : bx) * 32;
    const int k0   = blockIdx.y * 32;
    const int tx = threadIdx.x;           // 0..31
    const int ty = threadIdx.y;           // 0..7
    #pragma unroll
    for (int i = 0; i < 4; i++) {
        const int k = k0 + ty + i * 8;
        t[ty + i*8][tx] = w[(size_t)k * N + n0 + tx];
    }
    __syncthreads();
    #pragma unroll
    for (int i = 0; i < 4; i++) {
        const int n = n0 + ty + i * 8;
        wT[(size_t)n * CDIM + k0 + tx] = __float2half(t[tx][ty + i*8]);
    }
}

// ---------------- fp16 1-term tensor-core GEMM, 4-stage cp.async -------------
// MODE 0 (QKV): scatter epilogue (+bias, q scale) -> fp16 q/k/v.
// MODE 1 (proj): plain +bias fp32 -> d_out.
#define BK  32
#define LDA 40                       // padded smem stride (fp16 elems)
#define TILE_B (128*LDA*2)           // 10240 bytes per tile
#define STAGE_B (2*TILE_B)           // A, B
#define NSTAGE 4
#define GEMM_SMEM (NSTAGE*STAGE_B)   // 81920 B

template<int MODE>
__global__ __launch_bounds__(256, 2)
void gemm_mma_kernel(const float* __restrict__ bias, float* __restrict__ C)
{
    extern __shared__ __align__(16) char dsm[];
    const uint32_t u0 = smem_u32(dsm);

    const __half* __restrict__ Ahi = MODE ? g_ahi : g_xhi;
    const __half* __restrict__ Bw  = MODE ? g_wprojT : g_wqkvT;

    const int tid = threadIdx.x;
    const int wid = tid >> 5;
    const int lid = tid & 31;
    const int wm  = wid & 1;         // 0..1  (M)
    const int wn  = wid >> 1;        // 0..3  (N)
    const int m0  = blockIdx.y * 128;
    const int n0  = blockIdx.x * 128;

    // gmem load mapping: 64 rows/pass, 8 fp16 (16B) per thread, 2 passes
    const int lrow = tid >> 2;            // 0..63
    const int lcol = (tid & 3) * 8;       // 0,8,16,24

    const size_t gA0 = (size_t)(m0 + lrow)      * CDIM + lcol;
    const size_t gA1 = (size_t)(m0 + lrow + 64) * CDIM + lcol;
    const size_t gB0 = (size_t)(n0 + lrow)      * CDIM + lcol;
    const size_t gB1 = (size_t)(n0 + lrow + 64) * CDIM + lcol;
    const uint32_t so0 = (uint32_t)((lrow        * LDA + lcol) * 2);
    const uint32_t so1 = (uint32_t)(((lrow + 64) * LDA + lcol) * 2);

    // ldmatrix lane addressing (R11 scheme)
    const int aRow  = wm * 64 + (lid & 15);
    const int aKoff = (lid >> 4) * 8;
    const int bRowX = wn * 32 + (lid & 7) + ((lid >> 4) * 8);
    const int bKoff = ((lid >> 3) & 1) * 8;

    float acc[4][4][4];
    #pragma unroll
    for (int t = 0; t < 4; t++)
        #pragma unroll
        for (int u = 0; u < 4; u++)
            #pragma unroll
            for (int e = 0; e < 4; e++) acc[t][u][e] = 0.f;

#define ISSUE(chunk, stage) do {                                          \
        const int _k0 = (chunk) * BK;                                     \
        const uint32_t _sb = u0 + (stage) * STAGE_B;                      \
        cp16(_sb + 0*TILE_B + so0, Ahi + gA0 + _k0);                      \
        cp16(_sb + 0*TILE_B + so1, Ahi + gA1 + _k0);                      \
        cp16(_sb + 1*TILE_B + so0, Bw  + gB0 + _k0);                      \
        cp16(_sb + 1*TILE_B + so1, Bw  + gB1 + _k0);                      \
        asm volatile("cp.async.commit_group;" ::: "memory");              \
    } while (0)

    const int steps = CDIM / BK;     // 32
    ISSUE(0, 0);
    ISSUE(1, 1);
    ISSUE(2, 2);

    for (int c = 0; c < steps; c++) {
        if (c + 2 < steps)
            asm volatile("cp.async.wait_group 2;" ::: "memory");
        else if (c + 1 < steps)
            asm volatile("cp.async.wait_group 1;" ::: "memory");
        else
            asm volatile("cp.async.wait_group 0;" ::: "memory");
        __syncthreads();

        if (c + 3 < steps) ISSUE(c + 3, (c + 3) & 3);

        const uint32_t sb  = u0 + (c & 3) * STAGE_B;
        const uint32_t uAh = sb;
        const uint32_t uB  = sb + 1 * TILE_B;

        #pragma unroll
        for (int s = 0; s < 2; s++) {
            const int ak = aKoff + s * 16;
            const int bk = bKoff + s * 16;
            uint32_t ah[4][4], bw[2][4];   // bw[p] covers u=2p,2p+1

            #pragma unroll
            for (int t = 0; t < 4; t++)
                ldsm4(ah[t], uAh + (uint32_t)(((aRow + t*16) * LDA + ak) * 2));
            #pragma unroll
            for (int p = 0; p < 2; p++)
                ldsm4(bw[p], uB + (uint32_t)(((bRowX + p*16) * LDA + bk) * 2));

            #pragma unroll
            for (int t = 0; t < 4; t++)
                #pragma unroll
                for (int u = 0; u < 4; u++)
                    mma16816(acc[t][u], ah[t], &bw[u >> 1][(u & 1) * 2]);
        }
    }
#undef ISSUE

    // ---- epilogue (pairs share m, consecutive n) ----
    const int g   = lid >> 2;      // 0..7
    const int tig = lid & 3;       // 0..3
    #pragma unroll
    for (int t = 0; t < 4; t++) {
        #pragma unroll
        for (int u = 0; u < 4; u++) {
            #pragma unroll
            for (int ep = 0; ep < 2; ep++) {
                const int m = m0 + wm*64 + t*16 + g + (ep ? 8 : 0);
                const int n = n0 + wn*32 + u*8 + tig*2;
                float2 v2;
                v2.x = acc[t][u][ep*2 + 0] + bias[n];
                v2.y = acc[t][u][ep*2 + 1] + bias[n + 1];
                if (MODE == 0) {
                    const int b_  = m >> 12;
                    const int l   = m & (LL - 1);
                    const int wch = n >> 10;
                    const int rem = n & 1023;
                    const int h   = rem >> 6;
                    const int dd  = rem & 63;
                    const size_t idx = (((size_t)(b_ * NH + h)) * LL + l) * HD + dd;
                    if (wch == 0) {
                        __half2 hv = __halves2half2(__float2half(v2.x * QK_SCALE),
                                                    __float2half(v2.y * QK_SCALE));
                        *(__half2*)&g_q[idx] = hv;
                    } else if (wch == 1) {
                        *(__half2*)&g_k[idx] = __halves2half2(__float2half(v2.x),
                                                              __float2half(v2.y));
                    } else {
                        *(__half2*)&g_v[idx] = __halves2half2(__float2half(v2.x),
                                                              __float2half(v2.y));
                    }
                } else {
                    *(float2*)&C[(size_t)m * CDIM + n] = v2;
                }
            }
        }
    }
}

// ---------------- NA1D attention: fp16 smem tiles (half LDS bytes) ----------
#define TROWS 140
#define ROWPH 72   // halves per row: 144B = 9x16B chunks -> conflict-free

__global__ __launch_bounds__(128, 1)
void na1d_kernel(const float* __restrict__ rpb)
{
    __shared__ __align__(16) __half ksh[TROWS * ROWPH];
    __shared__ __align__(16) __half vsh[TROWS * ROWPH];
    __shared__ float rsh[RPB_W];

    const int tid = threadIdx.x;
    const int l0  = blockIdx.x * 128;
    const int h   = blockIdx.y;
    const int b   = blockIdx.z;

    const size_t head_base = ((size_t)(b * NH + h)) * LL * HD;
    const int kbase = min(max(l0 - (KW / 2), 0), LL - KW);
    const int krows = min(TROWS, LL - kbase);

    // ---- raw fp16 copy of K and V tiles (uint4 = 8 halves per load) ----
    const __half* kp = g_k + head_base + (size_t)kbase * HD;
    const __half* vp = g_v + head_base + (size_t)kbase * HD;
    for (int idx = tid; idx < krows * 8; idx += 128) {
        const int rr = idx >> 3;
        const int c8 = (idx & 7);
        *(uint4*)&ksh[rr * ROWPH + c8 * 8] = *(const uint4*)(kp + (size_t)rr * HD + c8 * 8);
        *(uint4*)&vsh[rr * ROWPH + c8 * 8] = *(const uint4*)(vp + (size_t)rr * HD + c8 * 8);
    }
    if (tid < RPB_W) rsh[tid] = rpb[h * RPB_W + tid];

    const int l = l0 + tid;
    // q in registers (fp16 gmem loads -> fp32); overlaps with smem fill
    float q[HD];
    {
        const __half* qp = g_q + head_base + (size_t)l * HD;
        #pragma unroll
        for (int c8 = 0; c8 < 8; c8++) {
            uint4 raw = *(const uint4*)(qp + c8 * 8);
            const __half2* h2 = (const __half2*)&raw;
            #pragma unroll
            for (int j = 0; j < 4; j++) {
                float2 f = __half22float2(h2[j]);
                q[c8*8 + j*2 + 0] = f.x;
                q[c8*8 + j*2 + 1] = f.y;
            }
        }
    }
    __syncthreads();

    const int ni = min(max(l - (KW / 2), 0), LL - KW);
    const int r0 = ni - kbase;
    const int bias0 = ni - l + (KW - 1);

    float logits[KW];
    #pragma unroll
    for (int kk = 0; kk < KW; kk++) {
        const __half* kr = &ksh[(r0 + kk) * ROWPH];
        float s = 0.f;
        #pragma unroll
        for (int c8 = 0; c8 < 8; c8++) {
            uint4 raw = *(const uint4*)(kr + c8 * 8);
            const __half2* h2 = (const __half2*)&raw;
            #pragma unroll
            for (int j = 0; j < 4; j++) {
                float2 f = __half22float2(h2[j]);
                s = fmaf(q[c8*8 + j*2 + 0], f.x, s);
                s = fmaf(q[c8*8 + j*2 + 1], f.y, s);
            }
        }
        logits[kk] = s + rsh[bias0 + kk];
    }

    float mx = logits[0];
    #pragma unroll
    for (int kk = 1; kk < KW; kk++) mx = fmaxf(mx, logits[kk]);
    float ssum = 0.f;
    #pragma unroll
    for (int kk = 0; kk < KW; kk++) { logits[kk] = expf(logits[kk] - mx); ssum += logits[kk]; }
    const float inv = 1.f / ssum;

    float acc[HD];
    #pragma unroll
    for (int d = 0; d < HD; d++) acc[d] = 0.f;
    #pragma unroll
    for (int kk = 0; kk < KW; kk++) {
        const float w = logits[kk] * inv;
        const __half* vr = &vsh[(r0 + kk) * ROWPH];
        #pragma unroll
        for (int c8 = 0; c8 < 8; c8++) {
            uint4 raw = *(const uint4*)(vr + c8 * 8);
            const __half2* h2 = (const __half2*)&raw;
            #pragma unroll
            for (int j = 0; j < 4; j++) {
                float2 f = __half22float2(h2[j]);
                acc[c8*8 + j*2 + 0] = fmaf(w, f.x, acc[c8*8 + j*2 + 0]);
                acc[c8*8 + j*2 + 1] = fmaf(w, f.y, acc[c8*8 + j*2 + 1]);
            }
        }
    }

    // ---- fp16 output: 8x 16B stores ----
    const size_t obase = ((size_t)b * LL + l) * CDIM + h * HD;
    uint4* oh4 = (uint4*)(g_ahi + obase);
    #pragma unroll
    for (int v8 = 0; v8 < 8; v8++) {        // 8 halves (16B) per iteration
        __half2 hh[4];
        #pragma unroll
        for (int j = 0; j < 4; j++)
            hh[j] = __halves2half2(__float2half(acc[v8*8 + j*2 + 0]),
                                   __float2half(acc[v8*8 + j*2 + 1]));
        uint4 hv;
        hv.x = *(uint32_t*)&hh[0]; hv.y = *(uint32_t*)&hh[1];
        hv.z = *(uint32_t*)&hh[2]; hv.w = *(uint32_t*)&hh[3];
        oh4[v8] = hv;
    }
}

// ---------------- launch ------------------------------------------------------
extern "C" void kernel_launch(void* const* d_in, const int* in_sizes, int n_in,
                              void* d_out, int out_size)
{
    const float* x      = (const float*)d_in[0];
    const float* w_qkv  = (const float*)d_in[1];
    const float* b_qkv  = (const float*)d_in[2];
    const float* rpb    = (const float*)d_in[3];
    const float* w_proj = (const float*)d_in[4];
    const float* b_proj = (const float*)d_in[5];
    float* out = (float*)d_out;

    cudaFuncSetAttribute(gemm_mma_kernel<0>, cudaFuncAttributeMaxDynamicSharedMemorySize, GEMM_SMEM);
    cudaFuncSetAttribute(gemm_mma_kernel<1>, cudaFuncAttributeMaxDynamicSharedMemorySize, GEMM_SMEM);

    // 0) convert x to fp16
    {
        const int n4 = MM * CDIM / 4;
        split_kernel<<<(n4 + 255) / 256, 256>>>(x, n4);
    }
    // 0b) transpose both weights -> fp16 [N,K] (single launch)
    {
        dim3 grid((NQKV + CDIM) / 32, CDIM / 32);
        transpose_both_kernel<<<grid, dim3(32, 8)>>>(w_qkv, w_proj);
    }

    // 1) QKV GEMM (tensor cores, 1-term) -> scatter fp16 q/k/v
    {
        dim3 grid(NQKV / 128, MM / 128);
        gemm_mma_kernel<0><<<grid, 256, GEMM_SMEM>>>(b_qkv, nullptr);
    }

    // 2) NA1D attention -> fp16 attn output
    {
        dim3 grid(LL / 128, NH, BB);
        na1d_kernel<<<grid, 128>>>(rpb);
    }

    // 3) proj GEMM (tensor cores, 1-term) -> d_out
    {
        dim3 grid(CDIM / 128, MM / 128);
        gemm_mma_kernel<1><<<grid, 256, GEMM_SMEM>>>(b_proj, out);
    }
}